// round 2
// baseline (speedup 1.0000x reference)
#include <cuda_runtime.h>
#include <cuda_bf16.h>

// Shapes (fixed for this problem)
#define D   1024
#define SEQ 2048
#define BATCH 4
#define MTOT (BATCH * SEQ)   // 8192

// Scratch (device globals: allocation-free rule)
__device__ float g_Q[BATCH * SEQ * D];
__device__ float g_K[BATCH * SEQ * D];
__device__ float g_V[BATCH * SEQ * D];
__device__ float g_P[BATCH * SEQ * SEQ];
__device__ float g_O[BATCH * SEQ * D];

#define BM 128
#define BN 128
#define BK 8
#define TM 8
#define TN 8

// C = alpha * A * op(B), per-z batch offsets sA/sB/sC.
//   BT=true : B is [N,K] row-major (C = A * B^T)
//   BT=false: B is [K,N] row-major (C = A * B)
//   CSKIP   : skip tiles strictly above the diagonal (causal scores)
//   CK      : truncate k-loop at (blockIdx.y+1)*BM (causal PV)
// All dims are multiples of the tile sizes for this problem; no guards needed.
template<bool BT, bool CSKIP, bool CK>
__global__ __launch_bounds__(256) void sgemm(const float* __restrict__ A,
                                             const float* __restrict__ B,
                                             float* __restrict__ C,
                                             int M, int N, int K,
                                             long sA, long sB, long sC,
                                             float alpha) {
    if (CSKIP && blockIdx.x > blockIdx.y) return;
    A += (long)blockIdx.z * sA;
    B += (long)blockIdx.z * sB;
    C += (long)blockIdx.z * sC;

    __shared__ float As[BK][BM];
    __shared__ float Bs[BK][BN];

    const int tid = threadIdx.x;
    const int tx = tid & 15;        // 0..15 (N direction)
    const int ty = tid >> 4;        // 0..15 (M direction)
    const int m0 = blockIdx.y * BM;
    const int n0 = blockIdx.x * BN;
    const int kEnd = CK ? min(K, (int)(blockIdx.y + 1) * BM) : K;

    // A-tile loader: thread -> (row 0..127, k-quad 0/4)
    const int arow = tid >> 1;
    const int acol = (tid & 1) * 4;
    const float* Aptr = A + (long)(m0 + arow) * K + acol;

    float acc[TM][TN];
    #pragma unroll
    for (int i = 0; i < TM; i++)
        #pragma unroll
        for (int j = 0; j < TN; j++) acc[i][j] = 0.f;

    for (int k0 = 0; k0 < kEnd; k0 += BK) {
        // ---- load A tile (transpose to [k][m]) ----
        float4 a = *(const float4*)(Aptr + k0);
        As[acol + 0][arow] = a.x;
        As[acol + 1][arow] = a.y;
        As[acol + 2][arow] = a.z;
        As[acol + 3][arow] = a.w;

        // ---- load B tile ----
        if (BT) {
            const float* Bp = B + (long)(n0 + arow) * K + k0 + acol;
            float4 b = *(const float4*)Bp;
            Bs[acol + 0][arow] = b.x;
            Bs[acol + 1][arow] = b.y;
            Bs[acol + 2][arow] = b.z;
            Bs[acol + 3][arow] = b.w;
        } else {
            const int brow = tid >> 5;          // 0..7  (k)
            const int bcol = (tid & 31) * 4;    // 0..124 (n)
            const float* Bp = B + (long)(k0 + brow) * N + n0 + bcol;
            *(float4*)&Bs[brow][bcol] = *(const float4*)Bp;
        }
        __syncthreads();

        #pragma unroll
        for (int kk = 0; kk < BK; kk++) {
            float ar[TM], br[TN];
            float4 a0 = *(const float4*)&As[kk][ty * TM];
            float4 a1 = *(const float4*)&As[kk][ty * TM + 4];
            ar[0]=a0.x; ar[1]=a0.y; ar[2]=a0.z; ar[3]=a0.w;
            ar[4]=a1.x; ar[5]=a1.y; ar[6]=a1.z; ar[7]=a1.w;
            float4 b0 = *(const float4*)&Bs[kk][tx * TN];
            float4 b1 = *(const float4*)&Bs[kk][tx * TN + 4];
            br[0]=b0.x; br[1]=b0.y; br[2]=b0.z; br[3]=b0.w;
            br[4]=b1.x; br[5]=b1.y; br[6]=b1.z; br[7]=b1.w;
            #pragma unroll
            for (int i = 0; i < TM; i++)
                #pragma unroll
                for (int j = 0; j < TN; j++)
                    acc[i][j] += ar[i] * br[j];
        }
        __syncthreads();
    }

    #pragma unroll
    for (int i = 0; i < TM; i++) {
        float* Cp = C + (long)(m0 + ty * TM + i) * N + n0 + tx * TN;
        float4 c0, c1;
        c0.x = alpha * acc[i][0]; c0.y = alpha * acc[i][1];
        c0.z = alpha * acc[i][2]; c0.w = alpha * acc[i][3];
        c1.x = alpha * acc[i][4]; c1.y = alpha * acc[i][5];
        c1.z = alpha * acc[i][6]; c1.w = alpha * acc[i][7];
        *(float4*)(Cp)     = c0;
        *(float4*)(Cp + 4) = c1;
    }
}

// Causal softmax over row i (valid j in [0, i]); zeros j > i so the PV GEMM
// can run dense. One block per (batch, row); P is [BATCH][SEQ][SEQ] contiguous,
// so flat row index addresses it directly.
__global__ __launch_bounds__(256) void softmax_causal(float* __restrict__ P) {
    const int row = blockIdx.x;           // b * SEQ + i
    const int i = row & (SEQ - 1);
    float* p = P + (long)row * SEQ;
    const int n = i + 1;
    const int tid = threadIdx.x;
    __shared__ float red[256];

    float m = -1e30f;
    for (int j = tid; j < n; j += 256) m = fmaxf(m, p[j]);
    red[tid] = m; __syncthreads();
    for (int s = 128; s > 0; s >>= 1) {
        if (tid < s) red[tid] = fmaxf(red[tid], red[tid + s]);
        __syncthreads();
    }
    m = red[0]; __syncthreads();

    float sum = 0.f;
    for (int j = tid; j < n; j += 256) {
        float e = expf(p[j] - m);
        p[j] = e;
        sum += e;
    }
    red[tid] = sum; __syncthreads();
    for (int s = 128; s > 0; s >>= 1) {
        if (tid < s) red[tid] += red[tid + s];
        __syncthreads();
    }
    const float inv = 1.f / red[0];

    for (int j = tid; j < n; j += 256) p[j] *= inv;
    for (int j = n + tid; j < SEQ; j += 256) p[j] = 0.f;
}

extern "C" void kernel_launch(void* const* d_in, const int* in_sizes, int n_in,
                              void* d_out, int out_size) {
    const float* Wk = (const float*)d_in[0];
    const float* Wq = (const float*)d_in[1];
    const float* Wv = (const float*)d_in[2];
    const float* Wo = (const float*)d_in[3];
    const float* x  = (const float*)d_in[4];
    float* out = (float*)d_out;

    float *Q, *K, *V, *P, *O;
    cudaGetSymbolAddress((void**)&Q, g_Q);
    cudaGetSymbolAddress((void**)&K, g_K);
    cudaGetSymbolAddress((void**)&V, g_V);
    cudaGetSymbolAddress((void**)&P, g_P);
    cudaGetSymbolAddress((void**)&O, g_O);

    const long SD = (long)SEQ * D;   // per-batch Q/K/V/O stride
    const long SS = (long)SEQ * SEQ; // per-batch P stride

    // 1) Projections: [8192,1024] = x @ W^T  (reference uses W.T here)
    {
        dim3 grid(D / BN, MTOT / BM, 1);
        sgemm<true, false, false><<<grid, 256>>>(x, Wq, Q, MTOT, D, D, 0, 0, 0, 1.f);
        sgemm<true, false, false><<<grid, 256>>>(x, Wk, K, MTOT, D, D, 0, 0, 0, 1.f);
        sgemm<true, false, false><<<grid, 256>>>(x, Wv, V, MTOT, D, D, 0, 0, 0, 1.f);
    }

    // 2) Scores: P = Q @ K^T / sqrt(D), batched, causal tile skip
    {
        dim3 grid(SEQ / BN, SEQ / BM, BATCH);
        sgemm<true, true, false><<<grid, 256>>>(Q, K, P, SEQ, SEQ, D,
                                                SD, SD, SS, 0.03125f);
    }

    // 3) Causal softmax (zero-fills upper triangle)
    softmax_causal<<<BATCH * SEQ, 256>>>(P);

    // 4) O = P @ V, batched, k-loop truncated by causality
    {
        dim3 grid(D / BN, SEQ / BM, BATCH);
        sgemm<false, false, true><<<grid, 256>>>(P, V, O, SEQ, D, SEQ,
                                                 SS, SD, SD, 1.f);
    }

    // 5) out = O @ Wo  — reference does `out @ out_proj` with NO transpose,
    //    so use the non-transposed-B GEMM (this was the R1 bug).
    {
        dim3 grid(D / BN, MTOT / BM, 1);
        sgemm<false, false, false><<<grid, 256>>>(O, Wo, out, MTOT, D, D, 0, 0, 0, 1.f);
    }
}

// round 6
// speedup vs baseline: 2.1506x; 2.1506x over previous
#include <cuda_runtime.h>
#include <cuda_bf16.h>
#include <cstdint>

#define D    1024
#define SEQ  2048
#define BATCH 4
#define MTOT (BATCH * SEQ)   // 8192

typedef __nv_bfloat16 bf16;

// ---------------- scratch (device globals; allocation-free rule) -------------
__device__ bf16  g_xh [MTOT * D], g_xl [MTOT * D];
__device__ bf16  g_wqh[D * D],    g_wql[D * D];
__device__ bf16  g_wkh[D * D],    g_wkl[D * D];
__device__ bf16  g_wvh[D * D],    g_wvl[D * D];
__device__ bf16  g_woth[D * D],   g_wotl[D * D];     // Wo^T planes
__device__ bf16  g_qh [MTOT * D], g_ql [MTOT * D];
__device__ bf16  g_kh [MTOT * D], g_kl [MTOT * D];
__device__ float g_vf [MTOT * D];
__device__ bf16  g_vth[MTOT * D], g_vtl[MTOT * D];   // V^T planes per batch [D][SEQ]
__device__ float g_pf [BATCH * SEQ * SEQ];
__device__ bf16  g_ph [BATCH * SEQ * SEQ], g_pl[BATCH * SEQ * SEQ];
__device__ bf16  g_oh [MTOT * D], g_ol [MTOT * D];

// ---------------- PTX helpers (sm_80-compatible only; NO tcgen05) -----------
__device__ __forceinline__ uint32_t smem_u32(const void* p) {
    uint32_t a;
    asm("{ .reg .u64 t; cvta.to.shared.u64 t, %1; cvt.u32.u64 %0, t; }"
        : "=r"(a) : "l"(p));
    return a;
}

__device__ __forceinline__ void cp16(uint32_t dst, const void* src) {
    asm volatile("cp.async.cg.shared.global [%0], [%1], 16;"
                 :: "r"(dst), "l"(src) : "memory");
}
#define CP_COMMIT() asm volatile("cp.async.commit_group;" ::: "memory")
#define CP_WAIT(n)  asm volatile("cp.async.wait_group %0;" :: "n"(n) : "memory")

__device__ __forceinline__ void ldm_x4(uint32_t& r0, uint32_t& r1,
                                       uint32_t& r2, uint32_t& r3, uint32_t a) {
    asm volatile("ldmatrix.sync.aligned.m8n8.x4.shared.b16 {%0,%1,%2,%3}, [%4];"
                 : "=r"(r0), "=r"(r1), "=r"(r2), "=r"(r3) : "r"(a));
}

__device__ __forceinline__ void mma16816(float& c0, float& c1, float& c2, float& c3,
                                         uint32_t a0, uint32_t a1, uint32_t a2, uint32_t a3,
                                         uint32_t b0, uint32_t b1) {
    asm volatile(
        "mma.sync.aligned.m16n8k16.row.col.f32.bf16.bf16.f32 "
        "{%0,%1,%2,%3}, {%4,%5,%6,%7}, {%8,%9}, {%0,%1,%2,%3};"
        : "+f"(c0), "+f"(c1), "+f"(c2), "+f"(c3)
        : "r"(a0), "r"(a1), "r"(a2), "r"(a3), "r"(b0), "r"(b1));
}

// ---------------- HMMA GEMM ---------------------------------------------------
// C[m][n] = alpha * sum_k A[m][k] * B[n][k]   (fp32 accumulate)
// 3-product Markidis split: Ah*Bh + Al*Bh + Ah*Bl (Al*Bl ~ 2^-18, dropped).
// A: [M][Krow] K-major, B: [N][Krow] K-major. BM=BN=128, BK=32, 3-stage cp.async.
// EPI=0: fp32 -> Cf.  EPI=1: bf16 hi/lo planes -> Ch/Cl.
// CSKIP: skip tiles strictly above diagonal. CK: truncate K at (by+1)*128.
#define ROWB   80u                 // padded SMEM row stride (32 bf16 + 8 pad)
#define TILEB  (128u * ROWB)       // 10240 B per operand tile
#define STAGEB (2u * TILEB)        // 20480 B per stage
#define DYN_SMEM (3 * 20480)       // 61440 B

template<bool CSKIP, bool CK, int EPI>
__global__ void __launch_bounds__(256) gemm_mma(
    const bf16* __restrict__ Ah, const bf16* __restrict__ Al,
    const bf16* __restrict__ Bh, const bf16* __restrict__ Bl,
    float* __restrict__ Cf, bf16* __restrict__ Ch, bf16* __restrict__ Cl,
    int Krow, int ldc, long sA, long sB, long sC, float alpha)
{
    if (CSKIP && blockIdx.x > blockIdx.y) return;

    extern __shared__ char dsm[];
    const uint32_t sbase = smem_u32(dsm);

    const int tid  = threadIdx.x;
    const int wid  = tid >> 5, lane = tid & 31;
    const int wm   = wid >> 2, wn = wid & 3;        // 2 x 4 warp grid
    const int m0   = blockIdx.y * 128;
    const int n0   = blockIdx.x * 128;

    Ah += blockIdx.z * sA;  Al += blockIdx.z * sA;
    Bh += blockIdx.z * sB;  Bl += blockIdx.z * sB;

    const int kEnd = CK ? min(Krow, (int)(blockIdx.y + 1) * 128) : Krow;
    const int nPer = kEnd >> 5;
    const int T    = 3 * nPer;      // 3 plane passes: (Ah,Bh), (Al,Bh), (Ah,Bl)

    // loader coords: thread handles rows (tid>>2) and (tid>>2)+64, chunk tid&3
    const int lrow = tid >> 2;
    const int lch  = tid & 3;

    float c[4][4][4];
    #pragma unroll
    for (int i = 0; i < 4; i++)
        #pragma unroll
        for (int j = 0; j < 4; j++)
            #pragma unroll
            for (int e = 0; e < 4; e++) c[i][j][e] = 0.f;

    // ---- tile load helper ----
    auto load_tile = [&](int t, int s) {
        const int plane = t / nPer;                 // 0,1,2
        const int k0    = (t - plane * nPer) << 5;
        const bf16* Ap = (plane == 1) ? Al : Ah;
        const bf16* Bp = (plane == 2) ? Bl : Bh;
        const uint32_t as = sbase + (uint32_t)s * STAGEB;
        const uint32_t bs = as + TILEB;
        #pragma unroll
        for (int h = 0; h < 2; h++) {
            const int row = lrow + h * 64;
            const uint32_t doff = (uint32_t)row * ROWB + (uint32_t)lch * 16u;
            cp16(as + doff, Ap + (size_t)(m0 + row) * Krow + k0 + lch * 8);
            cp16(bs + doff, Bp + (size_t)(n0 + row) * Krow + k0 + lch * 8);
        }
    };

    // prologue: stages 0,1
    load_tile(0, 0); CP_COMMIT();
    if (T > 1) { load_tile(1, 1); } CP_COMMIT();

    // ldmatrix lane addressing
    const uint32_t frow = ((lane >> 3) & 1) * 8 + (lane & 7);  // row-in-16
    const uint32_t fk   = ((lane >> 4) & 1) * 8;               // k-offset 0/8

    for (int t = 0; t < T; t++) {
        CP_WAIT(1);
        __syncthreads();

        if (t + 2 < T) load_tile(t + 2, (t + 2) % 3);
        CP_COMMIT();

        const int s = t % 3;
        const uint32_t as = sbase + (uint32_t)s * STAGEB;
        const uint32_t bs = as + TILEB;

        #pragma unroll
        for (int ks = 0; ks < 32; ks += 16) {
            uint32_t a[4][4], b[2][4];
            const uint32_t kcb = (uint32_t)(ks + fk) * 2u;
            #pragma unroll
            for (int i = 0; i < 4; i++)
                ldm_x4(a[i][0], a[i][1], a[i][2], a[i][3],
                       as + (uint32_t)(wm * 64 + i * 16 + frow) * ROWB + kcb);
            #pragma unroll
            for (int j = 0; j < 2; j++)
                ldm_x4(b[j][0], b[j][1], b[j][2], b[j][3],
                       bs + (uint32_t)(wn * 32 + j * 16 + frow) * ROWB + kcb);
            #pragma unroll
            for (int i = 0; i < 4; i++)
                #pragma unroll
                for (int jn = 0; jn < 4; jn++) {
                    const uint32_t* bb = b[jn >> 1];
                    const int sub = jn & 1;
                    mma16816(c[i][jn][0], c[i][jn][1], c[i][jn][2], c[i][jn][3],
                             a[i][0], a[i][1], a[i][2], a[i][3],
                             bb[sub], bb[sub + 2]);
                }
        }
        __syncthreads();
    }

    // ---- epilogue: accumulator quad layout -> direct global stores ----
    const int g   = lane >> 2;        // row within 8
    const int tg  = lane & 3;         // col pair
    const long zC = (long)blockIdx.z * sC;

    #pragma unroll
    for (int i = 0; i < 4; i++) {
        #pragma unroll
        for (int jn = 0; jn < 4; jn++) {
            const int row = m0 + wm * 64 + i * 16 + g;
            const int col = n0 + wn * 32 + jn * 8 + tg * 2;
            #pragma unroll
            for (int half = 0; half < 2; half++) {
                const size_t o = (size_t)(row + half * 8) * ldc + zC + col;
                const float v0 = alpha * c[i][jn][half * 2 + 0];
                const float v1 = alpha * c[i][jn][half * 2 + 1];
                if (EPI == 0) {
                    float2 f2; f2.x = v0; f2.y = v1;
                    *(float2*)(Cf + o) = f2;
                } else {
                    const bf16 h0 = __float2bfloat16(v0);
                    const bf16 h1 = __float2bfloat16(v1);
                    __nv_bfloat162 hh; hh.x = h0; hh.y = h1;
                    *(__nv_bfloat162*)(Ch + o) = hh;
                    __nv_bfloat162 ll;
                    ll.x = __float2bfloat16(v0 - __bfloat162float(h0));
                    ll.y = __float2bfloat16(v1 - __bfloat162float(h1));
                    *(__nv_bfloat162*)(Cl + o) = ll;
                }
            }
        }
    }
}

// ---------------- elementwise split fp32 -> bf16 hi/lo ----------------------
__global__ void __launch_bounds__(256) conv_split(const float* __restrict__ s,
                                                  bf16* __restrict__ h,
                                                  bf16* __restrict__ l, int n) {
    int i = blockIdx.x * 256 + threadIdx.x;
    if (i < n) {
        float v = s[i];
        bf16 hi = __float2bfloat16(v);
        h[i] = hi;
        l[i] = __float2bfloat16(v - __bfloat162float(hi));
    }
}

// ---------------- transpose + split: src [z][R][C] -> dst planes [z][C][R] --
__global__ void __launch_bounds__(256) transpose_split(
    const float* __restrict__ src, bf16* __restrict__ dh, bf16* __restrict__ dl,
    int R, int C, long sSrc, long sDst)
{
    __shared__ float t[32][33];
    const int tx = threadIdx.x, ty = threadIdx.y;   // 32 x 8
    const int x0 = blockIdx.x * 32;                 // over C
    const int y0 = blockIdx.y * 32;                 // over R
    const long zb = (long)blockIdx.z;

    #pragma unroll
    for (int j = 0; j < 4; j++)
        t[ty + j * 8][tx] = src[zb * sSrc + (size_t)(y0 + ty + j * 8) * C + x0 + tx];
    __syncthreads();

    #pragma unroll
    for (int j = 0; j < 4; j++) {
        const float v = t[tx][ty + j * 8];
        const size_t o = zb * sDst + (size_t)(x0 + ty + j * 8) * R + y0 + tx;
        const bf16 h = __float2bfloat16(v);
        dh[o] = h;
        dl[o] = __float2bfloat16(v - __bfloat162float(h));
    }
}

// ---------------- causal softmax (fp32 in, bf16 hi/lo planes out) -----------
__global__ void __launch_bounds__(256) softmax_causal(const float* __restrict__ P,
                                                      bf16* __restrict__ Ph,
                                                      bf16* __restrict__ Pl) {
    const int row = blockIdx.x;            // b * SEQ + i
    const int i = row & (SEQ - 1);
    const float* p = P + (size_t)row * SEQ;
    bf16* ph = Ph + (size_t)row * SEQ;
    bf16* pl = Pl + (size_t)row * SEQ;
    const int n = i + 1;
    const int tid = threadIdx.x;
    __shared__ float red[256];
    __shared__ float rowbuf[SEQ];          // 8KB — hold exp values

    float m = -1e30f;
    for (int j = tid; j < n; j += 256) m = fmaxf(m, p[j]);
    red[tid] = m; __syncthreads();
    for (int s = 128; s > 0; s >>= 1) {
        if (tid < s) red[tid] = fmaxf(red[tid], red[tid + s]);
        __syncthreads();
    }
    m = red[0]; __syncthreads();

    float sum = 0.f;
    for (int j = tid; j < n; j += 256) {
        float e = __expf(p[j] - m);
        rowbuf[j] = e;
        sum += e;
    }
    red[tid] = sum; __syncthreads();
    for (int s = 128; s > 0; s >>= 1) {
        if (tid < s) red[tid] += red[tid + s];
        __syncthreads();
    }
    const float inv = 1.f / red[0];
    __syncthreads();

    for (int j = tid; j < n; j += 256) {
        const float v = rowbuf[j] * inv;
        const bf16 h = __float2bfloat16(v);
        ph[j] = h;
        pl[j] = __float2bfloat16(v - __bfloat162float(h));
    }
    const bf16 z = __float2bfloat16(0.f);
    for (int j = n + tid; j < SEQ; j += 256) { ph[j] = z; pl[j] = z; }
}

// ---------------- launch -----------------------------------------------------
extern "C" void kernel_launch(void* const* d_in, const int* in_sizes, int n_in,
                              void* d_out, int out_size) {
    const float* Wk = (const float*)d_in[0];
    const float* Wq = (const float*)d_in[1];
    const float* Wv = (const float*)d_in[2];
    const float* Wo = (const float*)d_in[3];
    const float* x  = (const float*)d_in[4];
    float* out = (float*)d_out;

    bf16 *xh,*xl,*wqh,*wql,*wkh,*wkl,*wvh,*wvl,*woth,*wotl;
    bf16 *qh,*ql,*kh,*kl,*vth,*vtl,*ph,*pl,*oh,*ol;
    float *vf,*pf;
    cudaGetSymbolAddress((void**)&xh, g_xh);   cudaGetSymbolAddress((void**)&xl, g_xl);
    cudaGetSymbolAddress((void**)&wqh, g_wqh); cudaGetSymbolAddress((void**)&wql, g_wql);
    cudaGetSymbolAddress((void**)&wkh, g_wkh); cudaGetSymbolAddress((void**)&wkl, g_wkl);
    cudaGetSymbolAddress((void**)&wvh, g_wvh); cudaGetSymbolAddress((void**)&wvl, g_wvl);
    cudaGetSymbolAddress((void**)&woth, g_woth); cudaGetSymbolAddress((void**)&wotl, g_wotl);
    cudaGetSymbolAddress((void**)&qh, g_qh);   cudaGetSymbolAddress((void**)&ql, g_ql);
    cudaGetSymbolAddress((void**)&kh, g_kh);   cudaGetSymbolAddress((void**)&kl, g_kl);
    cudaGetSymbolAddress((void**)&vf, g_vf);
    cudaGetSymbolAddress((void**)&vth, g_vth); cudaGetSymbolAddress((void**)&vtl, g_vtl);
    cudaGetSymbolAddress((void**)&pf, g_pf);
    cudaGetSymbolAddress((void**)&ph, g_ph);   cudaGetSymbolAddress((void**)&pl, g_pl);
    cudaGetSymbolAddress((void**)&oh, g_oh);   cudaGetSymbolAddress((void**)&ol, g_ol);

    cudaFuncSetAttribute(gemm_mma<false,false,1>, cudaFuncAttributeMaxDynamicSharedMemorySize, DYN_SMEM);
    cudaFuncSetAttribute(gemm_mma<false,false,0>, cudaFuncAttributeMaxDynamicSharedMemorySize, DYN_SMEM);
    cudaFuncSetAttribute(gemm_mma<true ,false,0>, cudaFuncAttributeMaxDynamicSharedMemorySize, DYN_SMEM);
    cudaFuncSetAttribute(gemm_mma<false,true ,1>, cudaFuncAttributeMaxDynamicSharedMemorySize, DYN_SMEM);

    const long SD = (long)SEQ * D;
    const long SS = (long)SEQ * SEQ;

    // split inputs
    conv_split<<<(MTOT * D + 255) / 256, 256>>>(x, xh, xl, MTOT * D);
    conv_split<<<(D * D + 255) / 256, 256>>>(Wq, wqh, wql, D * D);
    conv_split<<<(D * D + 255) / 256, 256>>>(Wk, wkh, wkl, D * D);
    conv_split<<<(D * D + 255) / 256, 256>>>(Wv, wvh, wvl, D * D);
    transpose_split<<<dim3(32, 32, 1), dim3(32, 8)>>>(Wo, woth, wotl, D, D, 0, 0);

    // projections (W is [n_out, k_in] row-major => already K-major "B^T" form)
    gemm_mma<false,false,1><<<dim3(8, 64, 1), 256, DYN_SMEM>>>(
        xh, xl, wqh, wql, nullptr, qh, ql, D, D, 0, 0, 0, 1.f);
    gemm_mma<false,false,1><<<dim3(8, 64, 1), 256, DYN_SMEM>>>(
        xh, xl, wkh, wkl, nullptr, kh, kl, D, D, 0, 0, 0, 1.f);
    gemm_mma<false,false,0><<<dim3(8, 64, 1), 256, DYN_SMEM>>>(
        xh, xl, wvh, wvl, vf, nullptr, nullptr, D, D, 0, 0, 0, 1.f);

    // V^T planes per batch: [SEQ,D] -> [D,SEQ]
    transpose_split<<<dim3(D / 32, SEQ / 32, BATCH), dim3(32, 8)>>>(
        vf, vth, vtl, SEQ, D, SD, SD);

    // scores P = Q K^T / 32 (batched, causal tile-skip)
    gemm_mma<true,false,0><<<dim3(16, 16, BATCH), 256, DYN_SMEM>>>(
        qh, ql, kh, kl, pf, nullptr, nullptr, D, SEQ, SD, SD, SS, 0.03125f);

    // causal softmax -> P planes (zero-filled upper triangle)
    softmax_causal<<<BATCH * SEQ, 256>>>(pf, ph, pl);

    // O = P V (batched, causal K-truncation); B = V^T planes [D][SEQ]
    gemm_mma<false,true,1><<<dim3(8, 16, BATCH), 256, DYN_SMEM>>>(
        ph, pl, vth, vtl, nullptr, oh, ol, SEQ, D, SS, SD, SD, 1.f);

    // out = O Wo ; B = Wo^T planes [n][k]
    gemm_mma<false,false,0><<<dim3(8, 64, 1), 256, DYN_SMEM>>>(
        oh, ol, woth, wotl, out, nullptr, nullptr, D, D, 0, 0, 0, 1.f);
}

// round 7
// speedup vs baseline: 2.2004x; 1.0232x over previous
#include <cuda_runtime.h>
#include <cuda_bf16.h>
#include <cstdint>

#define D    1024
#define SEQ  2048
#define BATCH 4
#define MTOT (BATCH * SEQ)   // 8192

typedef __nv_bfloat16 bf16;

// ---------------- scratch (device globals; allocation-free rule) -------------
__device__ bf16  g_xh [MTOT * D], g_xl [MTOT * D];
__device__ bf16  g_wqh[D * D],    g_wql[D * D];
__device__ bf16  g_wkh[D * D],    g_wkl[D * D];
__device__ bf16  g_wvh[D * D],    g_wvl[D * D];
__device__ bf16  g_woth[D * D],   g_wotl[D * D];     // Wo^T planes
__device__ bf16  g_qh [MTOT * D], g_ql [MTOT * D];
__device__ bf16  g_kh [MTOT * D], g_kl [MTOT * D];
__device__ float g_vf [MTOT * D];
__device__ bf16  g_vth[MTOT * D], g_vtl[MTOT * D];   // V^T planes per batch [D][SEQ]
__device__ float g_pf [BATCH * SEQ * SEQ];
__device__ bf16  g_ph [BATCH * SEQ * SEQ], g_pl[BATCH * SEQ * SEQ];
__device__ bf16  g_oh [MTOT * D], g_ol [MTOT * D];

// ---------------- PTX helpers (sm_80-compatible only; NO tcgen05) -----------
__device__ __forceinline__ uint32_t smem_u32(const void* p) {
    uint32_t a;
    asm("{ .reg .u64 t; cvta.to.shared.u64 t, %1; cvt.u32.u64 %0, t; }"
        : "=r"(a) : "l"(p));
    return a;
}

__device__ __forceinline__ void cp16(uint32_t dst, const void* src) {
    asm volatile("cp.async.cg.shared.global [%0], [%1], 16;"
                 :: "r"(dst), "l"(src) : "memory");
}
#define CP_COMMIT() asm volatile("cp.async.commit_group;" ::: "memory")
#define CP_WAIT(n)  asm volatile("cp.async.wait_group %0;" :: "n"(n) : "memory")

__device__ __forceinline__ void ldm_x4(uint32_t& r0, uint32_t& r1,
                                       uint32_t& r2, uint32_t& r3, uint32_t a) {
    asm volatile("ldmatrix.sync.aligned.m8n8.x4.shared.b16 {%0,%1,%2,%3}, [%4];"
                 : "=r"(r0), "=r"(r1), "=r"(r2), "=r"(r3) : "r"(a));
}

__device__ __forceinline__ void mma16816(float& c0, float& c1, float& c2, float& c3,
                                         uint32_t a0, uint32_t a1, uint32_t a2, uint32_t a3,
                                         uint32_t b0, uint32_t b1) {
    asm volatile(
        "mma.sync.aligned.m16n8k16.row.col.f32.bf16.bf16.f32 "
        "{%0,%1,%2,%3}, {%4,%5,%6,%7}, {%8,%9}, {%0,%1,%2,%3};"
        : "+f"(c0), "+f"(c1), "+f"(c2), "+f"(c3)
        : "r"(a0), "r"(a1), "r"(a2), "r"(a3), "r"(b0), "r"(b1));
}

// ---------------- HMMA GEMM (fused-plane 3-product) ---------------------------
// C[m][n] = alpha * sum_k A[m][k] * B[n][k]   (fp32 accumulate)
// Markidis split fused per k-slab: Ah*Bh + Al*Bh + Ah*Bl  (Al*Bl ~2^-18 dropped).
// Per stage holds all 4 plane tiles (Ah, Al, Bh, Bl). BM=BN=128, BK=32,
// 3-stage cp.async pipeline, single __syncthreads per iteration.
// EPI=0: fp32 -> Cf.  EPI=1: bf16 hi/lo planes -> Ch/Cl.
// CSKIP: skip tiles strictly above diagonal. CK: truncate K at (by+1)*128.
#define ROWB   80u                 // padded SMEM row stride (32 bf16 + 8 pad)
#define TILEB  (128u * ROWB)       // 10240 B per plane tile
#define STAGEB (4u * TILEB)        // 40960 B per stage (Ah, Al, Bh, Bl)
#define DYN_SMEM (3 * 40960)       // 122880 B

template<bool CSKIP, bool CK, int EPI>
__global__ void __launch_bounds__(256) gemm_mma(
    const bf16* __restrict__ Ah, const bf16* __restrict__ Al,
    const bf16* __restrict__ Bh, const bf16* __restrict__ Bl,
    float* __restrict__ Cf, bf16* __restrict__ Ch, bf16* __restrict__ Cl,
    int Krow, int ldc, long sA, long sB, long sC, float alpha)
{
    if (CSKIP && blockIdx.x > blockIdx.y) return;

    extern __shared__ char dsm[];
    const uint32_t sbase = smem_u32(dsm);

    const int tid  = threadIdx.x;
    const int wid  = tid >> 5, lane = tid & 31;
    const int wm   = wid >> 2, wn = wid & 3;        // 2 x 4 warp grid
    const int m0   = blockIdx.y * 128;
    const int n0   = blockIdx.x * 128;

    Ah += blockIdx.z * sA;  Al += blockIdx.z * sA;
    Bh += blockIdx.z * sB;  Bl += blockIdx.z * sB;

    const int kEnd = CK ? min(Krow, (int)(blockIdx.y + 1) * 128) : Krow;
    const int T    = kEnd >> 5;      // one fused iteration per 32-wide k-slab

    // loader coords: thread handles rows (tid>>2) and (tid>>2)+64, chunk tid&3
    const int lrow = tid >> 2;
    const int lch  = tid & 3;

    float c[4][4][4];
    #pragma unroll
    for (int i = 0; i < 4; i++)
        #pragma unroll
        for (int j = 0; j < 4; j++)
            #pragma unroll
            for (int e = 0; e < 4; e++) c[i][j][e] = 0.f;

    // ---- slab load: all 4 plane tiles for k-slab t into stage s ----
    auto load_slab = [&](int t, int s) {
        const int k0 = t << 5;
        const uint32_t st = sbase + (uint32_t)s * STAGEB;
        #pragma unroll
        for (int h = 0; h < 2; h++) {
            const int row = lrow + h * 64;
            const uint32_t doff = (uint32_t)row * ROWB + (uint32_t)lch * 16u;
            const size_t aoff = (size_t)(m0 + row) * Krow + k0 + lch * 8;
            const size_t boff = (size_t)(n0 + row) * Krow + k0 + lch * 8;
            cp16(st + doff,             Ah + aoff);
            cp16(st + TILEB + doff,     Al + aoff);
            cp16(st + 2 * TILEB + doff, Bh + boff);
            cp16(st + 3 * TILEB + doff, Bl + boff);
        }
    };

    // prologue: stages 0,1
    load_slab(0, 0); CP_COMMIT();
    if (T > 1) { load_slab(1, 1); } CP_COMMIT();

    // ldmatrix lane addressing
    const uint32_t frow = ((lane >> 3) & 1) * 8 + (lane & 7);  // row-in-16
    const uint32_t fk   = ((lane >> 4) & 1) * 8;               // k-offset 0/8

    for (int t = 0; t < T; t++) {
        CP_WAIT(1);
        __syncthreads();
        // stage (t+2)%3 was last READ in iteration t-1; every warp passed this
        // sync only after finishing t-1's compute, so overwriting it is safe.
        if (t + 2 < T) load_slab(t + 2, (t + 2) % 3);
        CP_COMMIT();

        const uint32_t st = sbase + (uint32_t)(t % 3) * STAGEB;
        const uint32_t ahs = st;
        const uint32_t als = st + TILEB;
        const uint32_t bhs = st + 2 * TILEB;
        const uint32_t bls = st + 3 * TILEB;

        #pragma unroll
        for (int ks = 0; ks < 32; ks += 16) {
            uint32_t ah[4][4], al[4][4], bh[2][4], bl[2][4];
            const uint32_t kcb = (uint32_t)(ks + fk) * 2u;
            #pragma unroll
            for (int i = 0; i < 4; i++) {
                const uint32_t ro = (uint32_t)(wm * 64 + i * 16 + frow) * ROWB + kcb;
                ldm_x4(ah[i][0], ah[i][1], ah[i][2], ah[i][3], ahs + ro);
                ldm_x4(al[i][0], al[i][1], al[i][2], al[i][3], als + ro);
            }
            #pragma unroll
            for (int j = 0; j < 2; j++) {
                const uint32_t ro = (uint32_t)(wn * 32 + j * 16 + frow) * ROWB + kcb;
                ldm_x4(bh[j][0], bh[j][1], bh[j][2], bh[j][3], bhs + ro);
                ldm_x4(bl[j][0], bl[j][1], bl[j][2], bl[j][3], bls + ro);
            }
            #pragma unroll
            for (int i = 0; i < 4; i++)
                #pragma unroll
                for (int jn = 0; jn < 4; jn++) {
                    const int jh = jn >> 1, sub = jn & 1;
                    float* cc = c[i][jn];
                    // (Ah,Bh)
                    mma16816(cc[0], cc[1], cc[2], cc[3],
                             ah[i][0], ah[i][1], ah[i][2], ah[i][3],
                             bh[jh][sub], bh[jh][sub + 2]);
                    // (Al,Bh)
                    mma16816(cc[0], cc[1], cc[2], cc[3],
                             al[i][0], al[i][1], al[i][2], al[i][3],
                             bh[jh][sub], bh[jh][sub + 2]);
                    // (Ah,Bl)
                    mma16816(cc[0], cc[1], cc[2], cc[3],
                             ah[i][0], ah[i][1], ah[i][2], ah[i][3],
                             bl[jh][sub], bl[jh][sub + 2]);
                }
        }
        // no bottom sync: top-of-loop sync of iteration t+1 provides the
        // ordering before any warp's cp.async can touch this stage again.
    }

    // ---- epilogue: accumulator quad layout -> direct global stores ----
    const int g   = lane >> 2;        // row within 8
    const int tg  = lane & 3;         // col pair
    const long zC = (long)blockIdx.z * sC;

    #pragma unroll
    for (int i = 0; i < 4; i++) {
        #pragma unroll
        for (int jn = 0; jn < 4; jn++) {
            const int row = m0 + wm * 64 + i * 16 + g;
            const int col = n0 + wn * 32 + jn * 8 + tg * 2;
            #pragma unroll
            for (int half = 0; half < 2; half++) {
                const size_t o = (size_t)(row + half * 8) * ldc + zC + col;
                const float v0 = alpha * c[i][jn][half * 2 + 0];
                const float v1 = alpha * c[i][jn][half * 2 + 1];
                if (EPI == 0) {
                    float2 f2; f2.x = v0; f2.y = v1;
                    *(float2*)(Cf + o) = f2;
                } else {
                    const bf16 h0 = __float2bfloat16(v0);
                    const bf16 h1 = __float2bfloat16(v1);
                    __nv_bfloat162 hh; hh.x = h0; hh.y = h1;
                    *(__nv_bfloat162*)(Ch + o) = hh;
                    __nv_bfloat162 ll;
                    ll.x = __float2bfloat16(v0 - __bfloat162float(h0));
                    ll.y = __float2bfloat16(v1 - __bfloat162float(h1));
                    *(__nv_bfloat162*)(Cl + o) = ll;
                }
            }
        }
    }
}

// ---------------- elementwise split fp32 -> bf16 hi/lo ----------------------
__global__ void __launch_bounds__(256) conv_split(const float* __restrict__ s,
                                                  bf16* __restrict__ h,
                                                  bf16* __restrict__ l, int n) {
    int i = blockIdx.x * 256 + threadIdx.x;
    if (i < n) {
        float v = s[i];
        bf16 hi = __float2bfloat16(v);
        h[i] = hi;
        l[i] = __float2bfloat16(v - __bfloat162float(hi));
    }
}

// ---------------- transpose + split: src [z][R][C] -> dst planes [z][C][R] --
__global__ void __launch_bounds__(256) transpose_split(
    const float* __restrict__ src, bf16* __restrict__ dh, bf16* __restrict__ dl,
    int R, int C, long sSrc, long sDst)
{
    __shared__ float t[32][33];
    const int tx = threadIdx.x, ty = threadIdx.y;   // 32 x 8
    const int x0 = blockIdx.x * 32;                 // over C
    const int y0 = blockIdx.y * 32;                 // over R
    const long zb = (long)blockIdx.z;

    #pragma unroll
    for (int j = 0; j < 4; j++)
        t[ty + j * 8][tx] = src[zb * sSrc + (size_t)(y0 + ty + j * 8) * C + x0 + tx];
    __syncthreads();

    #pragma unroll
    for (int j = 0; j < 4; j++) {
        const float v = t[tx][ty + j * 8];
        const size_t o = zb * sDst + (size_t)(x0 + ty + j * 8) * R + y0 + tx;
        const bf16 h = __float2bfloat16(v);
        dh[o] = h;
        dl[o] = __float2bfloat16(v - __bfloat162float(h));
    }
}

// ---------------- causal softmax (fp32 in, bf16 hi/lo planes out) -----------
__global__ void __launch_bounds__(256) softmax_causal(const float* __restrict__ P,
                                                      bf16* __restrict__ Ph,
                                                      bf16* __restrict__ Pl) {
    const int row = blockIdx.x;            // b * SEQ + i
    const int i = row & (SEQ - 1);
    const float* p = P + (size_t)row * SEQ;
    bf16* ph = Ph + (size_t)row * SEQ;
    bf16* pl = Pl + (size_t)row * SEQ;
    const int n = i + 1;
    const int tid = threadIdx.x;
    __shared__ float red[256];
    __shared__ float rowbuf[SEQ];          // 8KB — hold exp values

    float m = -1e30f;
    for (int j = tid; j < n; j += 256) m = fmaxf(m, p[j]);
    red[tid] = m; __syncthreads();
    for (int s = 128; s > 0; s >>= 1) {
        if (tid < s) red[tid] = fmaxf(red[tid], red[tid + s]);
        __syncthreads();
    }
    m = red[0]; __syncthreads();

    float sum = 0.f;
    for (int j = tid; j < n; j += 256) {
        float e = __expf(p[j] - m);
        rowbuf[j] = e;
        sum += e;
    }
    red[tid] = sum; __syncthreads();
    for (int s = 128; s > 0; s >>= 1) {
        if (tid < s) red[tid] += red[tid + s];
        __syncthreads();
    }
    const float inv = 1.f / red[0];
    __syncthreads();

    for (int j = tid; j < n; j += 256) {
        const float v = rowbuf[j] * inv;
        const bf16 h = __float2bfloat16(v);
        ph[j] = h;
        pl[j] = __float2bfloat16(v - __bfloat162float(h));
    }
    const bf16 z = __float2bfloat16(0.f);
    for (int j = n + tid; j < SEQ; j += 256) { ph[j] = z; pl[j] = z; }
}

// ---------------- launch -----------------------------------------------------
extern "C" void kernel_launch(void* const* d_in, const int* in_sizes, int n_in,
                              void* d_out, int out_size) {
    const float* Wk = (const float*)d_in[0];
    const float* Wq = (const float*)d_in[1];
    const float* Wv = (const float*)d_in[2];
    const float* Wo = (const float*)d_in[3];
    const float* x  = (const float*)d_in[4];
    float* out = (float*)d_out;

    bf16 *xh,*xl,*wqh,*wql,*wkh,*wkl,*wvh,*wvl,*woth,*wotl;
    bf16 *qh,*ql,*kh,*kl,*vth,*vtl,*ph,*pl,*oh,*ol;
    float *vf,*pf;
    cudaGetSymbolAddress((void**)&xh, g_xh);   cudaGetSymbolAddress((void**)&xl, g_xl);
    cudaGetSymbolAddress((void**)&wqh, g_wqh); cudaGetSymbolAddress((void**)&wql, g_wql);
    cudaGetSymbolAddress((void**)&wkh, g_wkh); cudaGetSymbolAddress((void**)&wkl, g_wkl);
    cudaGetSymbolAddress((void**)&wvh, g_wvh); cudaGetSymbolAddress((void**)&wvl, g_wvl);
    cudaGetSymbolAddress((void**)&woth, g_woth); cudaGetSymbolAddress((void**)&wotl, g_wotl);
    cudaGetSymbolAddress((void**)&qh, g_qh);   cudaGetSymbolAddress((void**)&ql, g_ql);
    cudaGetSymbolAddress((void**)&kh, g_kh);   cudaGetSymbolAddress((void**)&kl, g_kl);
    cudaGetSymbolAddress((void**)&vf, g_vf);
    cudaGetSymbolAddress((void**)&vth, g_vth); cudaGetSymbolAddress((void**)&vtl, g_vtl);
    cudaGetSymbolAddress((void**)&pf, g_pf);
    cudaGetSymbolAddress((void**)&ph, g_ph);   cudaGetSymbolAddress((void**)&pl, g_pl);
    cudaGetSymbolAddress((void**)&oh, g_oh);   cudaGetSymbolAddress((void**)&ol, g_ol);

    cudaFuncSetAttribute(gemm_mma<false,false,1>, cudaFuncAttributeMaxDynamicSharedMemorySize, DYN_SMEM);
    cudaFuncSetAttribute(gemm_mma<false,false,0>, cudaFuncAttributeMaxDynamicSharedMemorySize, DYN_SMEM);
    cudaFuncSetAttribute(gemm_mma<true ,false,0>, cudaFuncAttributeMaxDynamicSharedMemorySize, DYN_SMEM);
    cudaFuncSetAttribute(gemm_mma<false,true ,1>, cudaFuncAttributeMaxDynamicSharedMemorySize, DYN_SMEM);

    const long SD = (long)SEQ * D;
    const long SS = (long)SEQ * SEQ;

    // split inputs
    conv_split<<<(MTOT * D + 255) / 256, 256>>>(x, xh, xl, MTOT * D);
    conv_split<<<(D * D + 255) / 256, 256>>>(Wq, wqh, wql, D * D);
    conv_split<<<(D * D + 255) / 256, 256>>>(Wk, wkh, wkl, D * D);
    conv_split<<<(D * D + 255) / 256, 256>>>(Wv, wvh, wvl, D * D);
    transpose_split<<<dim3(32, 32, 1), dim3(32, 8)>>>(Wo, woth, wotl, D, D, 0, 0);

    // projections (W is [n_out, k_in] row-major => already K-major "B^T" form)
    gemm_mma<false,false,1><<<dim3(8, 64, 1), 256, DYN_SMEM>>>(
        xh, xl, wqh, wql, nullptr, qh, ql, D, D, 0, 0, 0, 1.f);
    gemm_mma<false,false,1><<<dim3(8, 64, 1), 256, DYN_SMEM>>>(
        xh, xl, wkh, wkl, nullptr, kh, kl, D, D, 0, 0, 0, 1.f);
    gemm_mma<false,false,0><<<dim3(8, 64, 1), 256, DYN_SMEM>>>(
        xh, xl, wvh, wvl, vf, nullptr, nullptr, D, D, 0, 0, 0, 1.f);

    // V^T planes per batch: [SEQ,D] -> [D,SEQ]
    transpose_split<<<dim3(D / 32, SEQ / 32, BATCH), dim3(32, 8)>>>(
        vf, vth, vtl, SEQ, D, SD, SD);

    // scores P = Q K^T / 32 (batched, causal tile-skip)
    gemm_mma<true,false,0><<<dim3(16, 16, BATCH), 256, DYN_SMEM>>>(
        qh, ql, kh, kl, pf, nullptr, nullptr, D, SEQ, SD, SD, SS, 0.03125f);

    // causal softmax -> P planes (zero-filled upper triangle)
    softmax_causal<<<BATCH * SEQ, 256>>>(pf, ph, pl);

    // O = P V (batched, causal K-truncation); B = V^T planes [D][SEQ]
    gemm_mma<false,true,1><<<dim3(8, 16, BATCH), 256, DYN_SMEM>>>(
        ph, pl, vth, vtl, nullptr, oh, ol, SEQ, D, SS, SD, SD, 1.f);

    // out = O Wo ; B = Wo^T planes [n][k]
    gemm_mma<false,false,0><<<dim3(8, 64, 1), 256, DYN_SMEM>>>(
        oh, ol, woth, wotl, out, nullptr, nullptr, D, D, 0, 0, 0, 1.f);
}

// round 8
// speedup vs baseline: 2.3459x; 1.0661x over previous
#include <cuda_runtime.h>
#include <cuda_bf16.h>
#include <cstdint>

#define D    1024
#define SEQ  2048
#define BATCH 4
#define MTOT (BATCH * SEQ)   // 8192

typedef __nv_bfloat16 bf16;

// ---------------- scratch (device globals; allocation-free rule) -------------
__device__ bf16  g_xh [MTOT * D], g_xl [MTOT * D];
__device__ bf16  g_wqh[D * D],    g_wql[D * D];
__device__ bf16  g_wkh[D * D],    g_wkl[D * D];
__device__ bf16  g_wvh[D * D],    g_wvl[D * D];
__device__ bf16  g_woth[D * D],   g_wotl[D * D];     // Wo^T planes
__device__ bf16  g_qh [MTOT * D], g_ql [MTOT * D];
__device__ bf16  g_kh [MTOT * D], g_kl [MTOT * D];
__device__ float g_vf [MTOT * D];
__device__ bf16  g_vth[MTOT * D], g_vtl[MTOT * D];   // V^T planes per batch [D][SEQ]
__device__ float g_pf [BATCH * SEQ * SEQ];
__device__ bf16  g_ph [BATCH * SEQ * SEQ], g_pl[BATCH * SEQ * SEQ];
__device__ bf16  g_oh [MTOT * D], g_ol [MTOT * D];

// ---------------- PTX helpers (sm_80-compatible only; NO tcgen05) -----------
__device__ __forceinline__ uint32_t smem_u32(const void* p) {
    uint32_t a;
    asm("{ .reg .u64 t; cvta.to.shared.u64 t, %1; cvt.u32.u64 %0, t; }"
        : "=r"(a) : "l"(p));
    return a;
}

__device__ __forceinline__ void cp16(uint32_t dst, const void* src) {
    asm volatile("cp.async.cg.shared.global [%0], [%1], 16;"
                 :: "r"(dst), "l"(src) : "memory");
}
#define CP_COMMIT() asm volatile("cp.async.commit_group;" ::: "memory")
#define CP_WAIT(n)  asm volatile("cp.async.wait_group %0;" :: "n"(n) : "memory")

__device__ __forceinline__ void ldm_x4(uint32_t& r0, uint32_t& r1,
                                       uint32_t& r2, uint32_t& r3, uint32_t a) {
    asm volatile("ldmatrix.sync.aligned.m8n8.x4.shared.b16 {%0,%1,%2,%3}, [%4];"
                 : "=r"(r0), "=r"(r1), "=r"(r2), "=r"(r3) : "r"(a));
}

__device__ __forceinline__ void mma16816(float& c0, float& c1, float& c2, float& c3,
                                         uint32_t a0, uint32_t a1, uint32_t a2, uint32_t a3,
                                         uint32_t b0, uint32_t b1) {
    asm volatile(
        "mma.sync.aligned.m16n8k16.row.col.f32.bf16.bf16.f32 "
        "{%0,%1,%2,%3}, {%4,%5,%6,%7}, {%8,%9}, {%0,%1,%2,%3};"
        : "+f"(c0), "+f"(c1), "+f"(c2), "+f"(c3)
        : "r"(a0), "r"(a1), "r"(a2), "r"(a3), "r"(b0), "r"(b1));
}

// ---------------- HMMA GEMM (fused-plane 3-product) ---------------------------
// C[m][n] = alpha * sum_k A[m][k] * B[n][k]   (fp32 accumulate)
// Markidis split fused per k-slab: Ah*Bh + Al*Bh + Ah*Bl  (Al*Bl ~2^-18 dropped).
// EPI=0: fp32 -> Cf.  EPI=1: bf16 hi/lo planes -> Ch/Cl.
// EPI=3: merged QKV mode — blockIdx.z selects B planes (z0: Bh/Bl, z1: Bh2/Bl2,
//        z2: Bh3/Bl3) and output (z0: Ch/Cl, z1: Ch2/Cl2, z2: fp32 Cf).
// CSKIP: skip tiles strictly above diagonal. CK: truncate K at (by+1)*128.
// CSKIP/CK use a (5*by)%16 bijection on blockIdx.y so long- and short-running
// CTAs interleave in launch order (last-wave load balance).
#define ROWB   80u                 // padded SMEM row stride (32 bf16 + 8 pad)
#define TILEB  (128u * ROWB)       // 10240 B per plane tile
#define STAGEB (4u * TILEB)        // 40960 B per stage (Ah, Al, Bh, Bl)
#define DYN_SMEM (3 * 40960)       // 122880 B

template<bool CSKIP, bool CK, int EPI>
__global__ void __launch_bounds__(256) gemm_mma(
    const bf16* __restrict__ Ah, const bf16* __restrict__ Al,
    const bf16* __restrict__ Bh, const bf16* __restrict__ Bl,
    float* __restrict__ Cf, bf16* __restrict__ Ch, bf16* __restrict__ Cl,
    const bf16* __restrict__ Bh2, const bf16* __restrict__ Bl2,
    const bf16* __restrict__ Bh3, const bf16* __restrict__ Bl3,
    bf16* __restrict__ Ch2, bf16* __restrict__ Cl2,
    int Krow, int ldc, long sA, long sB, long sC, float alpha)
{
    // launch-order balance permutation for causal grids (grid.y == 16)
    const int by = (CSKIP || CK) ? (int)((blockIdx.y * 5u) & 15u)
                                 : (int)blockIdx.y;
    if (CSKIP && (int)blockIdx.x > by) return;

    extern __shared__ char dsm[];
    const uint32_t sbase = smem_u32(dsm);

    const int tid  = threadIdx.x;
    const int wid  = tid >> 5, lane = tid & 31;
    const int wm   = wid >> 2, wn = wid & 3;        // 2 x 4 warp grid
    const int m0   = by * 128;
    const int n0   = blockIdx.x * 128;
    const int zid  = blockIdx.z;

    const bf16* AhP = Ah + (long)zid * sA;
    const bf16* AlP = Al + (long)zid * sA;
    const bf16* BhP = Bh;
    const bf16* BlP = Bl;
    if (EPI == 3) {
        if (zid == 1)      { BhP = Bh2; BlP = Bl2; }
        else if (zid == 2) { BhP = Bh3; BlP = Bl3; }
    } else {
        BhP += (long)zid * sB;
        BlP += (long)zid * sB;
    }

    const int kEnd = CK ? min(Krow, (by + 1) * 128) : Krow;
    const int T    = kEnd >> 5;      // one fused iteration per 32-wide k-slab

    // loader coords: thread handles rows (tid>>2) and (tid>>2)+64, chunk tid&3
    const int lrow = tid >> 2;
    const int lch  = tid & 3;

    float c[4][4][4];
    #pragma unroll
    for (int i = 0; i < 4; i++)
        #pragma unroll
        for (int j = 0; j < 4; j++)
            #pragma unroll
            for (int e = 0; e < 4; e++) c[i][j][e] = 0.f;

    // ---- slab load: all 4 plane tiles for k-slab t into stage s ----
    auto load_slab = [&](int t, int s) {
        const int k0 = t << 5;
        const uint32_t st = sbase + (uint32_t)s * STAGEB;
        #pragma unroll
        for (int h = 0; h < 2; h++) {
            const int row = lrow + h * 64;
            const uint32_t doff = (uint32_t)row * ROWB + (uint32_t)lch * 16u;
            const size_t aoff = (size_t)(m0 + row) * Krow + k0 + lch * 8;
            const size_t boff = (size_t)(n0 + row) * Krow + k0 + lch * 8;
            cp16(st + doff,             AhP + aoff);
            cp16(st + TILEB + doff,     AlP + aoff);
            cp16(st + 2 * TILEB + doff, BhP + boff);
            cp16(st + 3 * TILEB + doff, BlP + boff);
        }
    };

    // prologue: stages 0,1
    load_slab(0, 0); CP_COMMIT();
    if (T > 1) { load_slab(1, 1); } CP_COMMIT();

    // ldmatrix lane addressing
    const uint32_t frow = ((lane >> 3) & 1) * 8 + (lane & 7);  // row-in-16
    const uint32_t fk   = ((lane >> 4) & 1) * 8;               // k-offset 0/8

    for (int t = 0; t < T; t++) {
        CP_WAIT(1);
        __syncthreads();
        // stage (t+2)%3 was last READ in iteration t-1; every warp passed this
        // sync only after finishing t-1's compute, so overwriting it is safe.
        if (t + 2 < T) load_slab(t + 2, (t + 2) % 3);
        CP_COMMIT();

        const uint32_t st = sbase + (uint32_t)(t % 3) * STAGEB;
        const uint32_t ahs = st;
        const uint32_t als = st + TILEB;
        const uint32_t bhs = st + 2 * TILEB;
        const uint32_t bls = st + 3 * TILEB;

        #pragma unroll
        for (int ks = 0; ks < 32; ks += 16) {
            uint32_t ah[4][4], al[4][4], bh[2][4], bl[2][4];
            const uint32_t kcb = (uint32_t)(ks + fk) * 2u;
            #pragma unroll
            for (int i = 0; i < 4; i++) {
                const uint32_t ro = (uint32_t)(wm * 64 + i * 16 + frow) * ROWB + kcb;
                ldm_x4(ah[i][0], ah[i][1], ah[i][2], ah[i][3], ahs + ro);
                ldm_x4(al[i][0], al[i][1], al[i][2], al[i][3], als + ro);
            }
            #pragma unroll
            for (int j = 0; j < 2; j++) {
                const uint32_t ro = (uint32_t)(wn * 32 + j * 16 + frow) * ROWB + kcb;
                ldm_x4(bh[j][0], bh[j][1], bh[j][2], bh[j][3], bhs + ro);
                ldm_x4(bl[j][0], bl[j][1], bl[j][2], bl[j][3], bls + ro);
            }
            #pragma unroll
            for (int i = 0; i < 4; i++)
                #pragma unroll
                for (int jn = 0; jn < 4; jn++) {
                    const int jh = jn >> 1, sub = jn & 1;
                    float* cc = c[i][jn];
                    mma16816(cc[0], cc[1], cc[2], cc[3],
                             ah[i][0], ah[i][1], ah[i][2], ah[i][3],
                             bh[jh][sub], bh[jh][sub + 2]);
                    mma16816(cc[0], cc[1], cc[2], cc[3],
                             al[i][0], al[i][1], al[i][2], al[i][3],
                             bh[jh][sub], bh[jh][sub + 2]);
                    mma16816(cc[0], cc[1], cc[2], cc[3],
                             ah[i][0], ah[i][1], ah[i][2], ah[i][3],
                             bl[jh][sub], bl[jh][sub + 2]);
                }
        }
        // no bottom sync: top-of-loop sync of iteration t+1 provides the
        // ordering before any warp's cp.async can touch this stage again.
    }

    // ---- epilogue: accumulator quad layout -> direct global stores ----
    const int g   = lane >> 2;        // row within 8
    const int tg  = lane & 3;         // col pair
    const long zC = (EPI == 3) ? 0 : (long)zid * sC;

    float*      CfP = Cf;
    bf16*       ChP = Ch;
    bf16*       ClP = Cl;
    if (EPI == 3 && zid == 1) { ChP = Ch2; ClP = Cl2; }
    const bool  fp32out = (EPI == 0) || (EPI == 3 && zid == 2);

    #pragma unroll
    for (int i = 0; i < 4; i++) {
        #pragma unroll
        for (int jn = 0; jn < 4; jn++) {
            const int row = m0 + wm * 64 + i * 16 + g;
            const int col = n0 + wn * 32 + jn * 8 + tg * 2;
            #pragma unroll
            for (int half = 0; half < 2; half++) {
                const size_t o = (size_t)(row + half * 8) * ldc + zC + col;
                const float v0 = alpha * c[i][jn][half * 2 + 0];
                const float v1 = alpha * c[i][jn][half * 2 + 1];
                if (fp32out) {
                    float2 f2; f2.x = v0; f2.y = v1;
                    *(float2*)(CfP + o) = f2;
                } else {
                    const bf16 h0 = __float2bfloat16(v0);
                    const bf16 h1 = __float2bfloat16(v1);
                    __nv_bfloat162 hh; hh.x = h0; hh.y = h1;
                    *(__nv_bfloat162*)(ChP + o) = hh;
                    __nv_bfloat162 ll;
                    ll.x = __float2bfloat16(v0 - __bfloat162float(h0));
                    ll.y = __float2bfloat16(v1 - __bfloat162float(h1));
                    *(__nv_bfloat162*)(ClP + o) = ll;
                }
            }
        }
    }
}

// ---------------- merged split: x + Wq + Wk + Wv in one launch ---------------
#define NX (MTOT * D)      // 8388608
#define NW (D * D)         // 1048576 = 2^20
__global__ void __launch_bounds__(256) conv_split_all(
    const float* __restrict__ x,  const float* __restrict__ wq,
    const float* __restrict__ wk, const float* __restrict__ wv,
    bf16* __restrict__ xh,  bf16* __restrict__ xl,
    bf16* __restrict__ qh_, bf16* __restrict__ ql_,
    bf16* __restrict__ kh_, bf16* __restrict__ kl_,
    bf16* __restrict__ vh_, bf16* __restrict__ vl_)
{
    long i = (long)blockIdx.x * 256 + threadIdx.x;
    const float* s; bf16 *h, *l; long j;
    if (i < NX) { s = x; h = xh; l = xl; j = i; }
    else {
        long r = i - NX;
        int seg = (int)(r >> 20);       // NW = 2^20
        j = r & (NW - 1);
        if (seg == 0)      { s = wq; h = qh_; l = ql_; }
        else if (seg == 1) { s = wk; h = kh_; l = kl_; }
        else               { s = wv; h = vh_; l = vl_; }
    }
    float v = s[j];
    bf16 hi = __float2bfloat16(v);
    h[j] = hi;
    l[j] = __float2bfloat16(v - __bfloat162float(hi));
}

// ---------------- transpose + split: src [z][R][C] -> dst planes [z][C][R] --
__global__ void __launch_bounds__(256) transpose_split(
    const float* __restrict__ src, bf16* __restrict__ dh, bf16* __restrict__ dl,
    int R, int C, long sSrc, long sDst)
{
    __shared__ float t[32][33];
    const int tx = threadIdx.x, ty = threadIdx.y;   // 32 x 8
    const int x0 = blockIdx.x * 32;                 // over C
    const int y0 = blockIdx.y * 32;                 // over R
    const long zb = (long)blockIdx.z;

    #pragma unroll
    for (int j = 0; j < 4; j++)
        t[ty + j * 8][tx] = src[zb * sSrc + (size_t)(y0 + ty + j * 8) * C + x0 + tx];
    __syncthreads();

    #pragma unroll
    for (int j = 0; j < 4; j++) {
        const float v = t[tx][ty + j * 8];
        const size_t o = zb * sDst + (size_t)(x0 + ty + j * 8) * R + y0 + tx;
        const bf16 h = __float2bfloat16(v);
        dh[o] = h;
        dl[o] = __float2bfloat16(v - __bfloat162float(h));
    }
}

// ---------------- causal softmax (fp32 in, bf16 hi/lo planes out) -----------
__global__ void __launch_bounds__(256) softmax_causal(const float* __restrict__ P,
                                                      bf16* __restrict__ Ph,
                                                      bf16* __restrict__ Pl) {
    const int row = blockIdx.x;            // b * SEQ + i
    const int i = row & (SEQ - 1);
    const float* p = P + (size_t)row * SEQ;
    bf16* ph = Ph + (size_t)row * SEQ;
    bf16* pl = Pl + (size_t)row * SEQ;
    const int n = i + 1;
    const int tid = threadIdx.x;
    __shared__ float red[256];
    __shared__ float rowbuf[SEQ];          // 8KB — hold exp values

    float m = -1e30f;
    for (int j = tid; j < n; j += 256) m = fmaxf(m, p[j]);
    red[tid] = m; __syncthreads();
    for (int s = 128; s > 0; s >>= 1) {
        if (tid < s) red[tid] = fmaxf(red[tid], red[tid + s]);
        __syncthreads();
    }
    m = red[0]; __syncthreads();

    float sum = 0.f;
    for (int j = tid; j < n; j += 256) {
        float e = __expf(p[j] - m);
        rowbuf[j] = e;
        sum += e;
    }
    red[tid] = sum; __syncthreads();
    for (int s = 128; s > 0; s >>= 1) {
        if (tid < s) red[tid] += red[tid + s];
        __syncthreads();
    }
    const float inv = 1.f / red[0];
    __syncthreads();

    for (int j = tid; j < n; j += 256) {
        const float v = rowbuf[j] * inv;
        const bf16 h = __float2bfloat16(v);
        ph[j] = h;
        pl[j] = __float2bfloat16(v - __bfloat162float(h));
    }
    const bf16 z = __float2bfloat16(0.f);
    for (int j = n + tid; j < SEQ; j += 256) { ph[j] = z; pl[j] = z; }
}

// ---------------- launch -----------------------------------------------------
extern "C" void kernel_launch(void* const* d_in, const int* in_sizes, int n_in,
                              void* d_out, int out_size) {
    const float* Wk = (const float*)d_in[0];
    const float* Wq = (const float*)d_in[1];
    const float* Wv = (const float*)d_in[2];
    const float* Wo = (const float*)d_in[3];
    const float* x  = (const float*)d_in[4];
    float* out = (float*)d_out;

    bf16 *xh,*xl,*wqh,*wql,*wkh,*wkl,*wvh,*wvl,*woth,*wotl;
    bf16 *qh,*ql,*kh,*kl,*vth,*vtl,*ph,*pl,*oh,*ol;
    float *vf,*pf;
    cudaGetSymbolAddress((void**)&xh, g_xh);   cudaGetSymbolAddress((void**)&xl, g_xl);
    cudaGetSymbolAddress((void**)&wqh, g_wqh); cudaGetSymbolAddress((void**)&wql, g_wql);
    cudaGetSymbolAddress((void**)&wkh, g_wkh); cudaGetSymbolAddress((void**)&wkl, g_wkl);
    cudaGetSymbolAddress((void**)&wvh, g_wvh); cudaGetSymbolAddress((void**)&wvl, g_wvl);
    cudaGetSymbolAddress((void**)&woth, g_woth); cudaGetSymbolAddress((void**)&wotl, g_wotl);
    cudaGetSymbolAddress((void**)&qh, g_qh);   cudaGetSymbolAddress((void**)&ql, g_ql);
    cudaGetSymbolAddress((void**)&kh, g_kh);   cudaGetSymbolAddress((void**)&kl, g_kl);
    cudaGetSymbolAddress((void**)&vf, g_vf);
    cudaGetSymbolAddress((void**)&vth, g_vth); cudaGetSymbolAddress((void**)&vtl, g_vtl);
    cudaGetSymbolAddress((void**)&pf, g_pf);
    cudaGetSymbolAddress((void**)&ph, g_ph);   cudaGetSymbolAddress((void**)&pl, g_pl);
    cudaGetSymbolAddress((void**)&oh, g_oh);   cudaGetSymbolAddress((void**)&ol, g_ol);

    cudaFuncSetAttribute(gemm_mma<false,false,3>, cudaFuncAttributeMaxDynamicSharedMemorySize, DYN_SMEM);
    cudaFuncSetAttribute(gemm_mma<false,false,0>, cudaFuncAttributeMaxDynamicSharedMemorySize, DYN_SMEM);
    cudaFuncSetAttribute(gemm_mma<true ,false,0>, cudaFuncAttributeMaxDynamicSharedMemorySize, DYN_SMEM);
    cudaFuncSetAttribute(gemm_mma<false,true ,1>, cudaFuncAttributeMaxDynamicSharedMemorySize, DYN_SMEM);

    const long SD = (long)SEQ * D;
    const long SS = (long)SEQ * SEQ;

    // split x + Wq + Wk + Wv in ONE launch
    conv_split_all<<<(NX + 3 * NW + 255) / 256, 256>>>(
        x, Wq, Wk, Wv, xh, xl, wqh, wql, wkh, wkl, wvh, wvl);
    transpose_split<<<dim3(32, 32, 1), dim3(32, 8)>>>(Wo, woth, wotl, D, D, 0, 0);

    // merged QKV projection: grid.z selects weight planes + output target
    //   z=0 -> Q planes (qh/ql), z=1 -> K planes (kh/kl), z=2 -> V fp32 (vf)
    gemm_mma<false,false,3><<<dim3(8, 64, 3), 256, DYN_SMEM>>>(
        xh, xl, wqh, wql, vf, qh, ql,
        wkh, wkl, wvh, wvl, kh, kl,
        D, D, 0, 0, 0, 1.f);

    // V^T planes per batch: [SEQ,D] -> [D,SEQ]
    transpose_split<<<dim3(D / 32, SEQ / 32, BATCH), dim3(32, 8)>>>(
        vf, vth, vtl, SEQ, D, SD, SD);

    // scores P = Q K^T / 32 (batched, causal tile-skip, by-permuted)
    gemm_mma<true,false,0><<<dim3(16, 16, BATCH), 256, DYN_SMEM>>>(
        qh, ql, kh, kl, pf, nullptr, nullptr,
        nullptr, nullptr, nullptr, nullptr, nullptr, nullptr,
        D, SEQ, SD, SD, SS, 0.03125f);

    // causal softmax -> P planes (zero-filled upper triangle)
    softmax_causal<<<BATCH * SEQ, 256>>>(pf, ph, pl);

    // O = P V (batched, causal K-truncation, by-permuted); B = V^T planes
    gemm_mma<false,true,1><<<dim3(8, 16, BATCH), 256, DYN_SMEM>>>(
        ph, pl, vth, vtl, nullptr, oh, ol,
        nullptr, nullptr, nullptr, nullptr, nullptr, nullptr,
        SEQ, D, SS, SD, SD, 1.f);

    // out = O Wo ; B = Wo^T planes [n][k]
    gemm_mma<false,false,0><<<dim3(8, 64, 1), 256, DYN_SMEM>>>(
        oh, ol, woth, wotl, out, nullptr, nullptr,
        nullptr, nullptr, nullptr, nullptr, nullptr, nullptr,
        D, D, 0, 0, 0, 1.f);
}

// round 10
// speedup vs baseline: 3.3819x; 1.4417x over previous
#include <cuda_runtime.h>
#include <cuda_fp16.h>
#include <cstdint>

#define D    1024
#define SEQ  2048
#define BATCH 4
#define MTOT (BATCH * SEQ)   // 8192

typedef __half fp16;

// ---------------- scratch (device globals; allocation-free rule) -------------
__device__ fp16  g_xh [MTOT * D], g_xl [MTOT * D];
__device__ fp16  g_wqh[D * D];                        // weight hi planes only
__device__ fp16  g_wkh[D * D];                        // (B-side lo never used
__device__ fp16  g_wvh[D * D];                        //  in 2-product scheme)
__device__ fp16  g_woth[D * D];                       // Wo^T hi plane
__device__ fp16  g_qh [MTOT * D], g_ql [MTOT * D];
__device__ fp16  g_kh [MTOT * D], g_kl [MTOT * D];
__device__ float g_vf [MTOT * D];
__device__ fp16  g_vth[MTOT * D];                     // V^T hi plane per batch [D][SEQ]
__device__ float g_pf [BATCH * SEQ * SEQ];
__device__ fp16  g_ph [BATCH * SEQ * SEQ], g_pl[BATCH * SEQ * SEQ];
__device__ fp16  g_oh [MTOT * D], g_ol [MTOT * D];

// ---------------- PTX helpers (sm_80-compatible only; NO tcgen05) -----------
__device__ __forceinline__ uint32_t smem_u32(const void* p) {
    uint32_t a;
    asm("{ .reg .u64 t; cvta.to.shared.u64 t, %1; cvt.u32.u64 %0, t; }"
        : "=r"(a) : "l"(p));
    return a;
}

__device__ __forceinline__ void cp16(uint32_t dst, const void* src) {
    asm volatile("cp.async.cg.shared.global [%0], [%1], 16;"
                 :: "r"(dst), "l"(src) : "memory");
}
#define CP_COMMIT() asm volatile("cp.async.commit_group;" ::: "memory")
#define CP_WAIT(n)  asm volatile("cp.async.wait_group %0;" :: "n"(n) : "memory")

__device__ __forceinline__ void ldm_x4(uint32_t& r0, uint32_t& r1,
                                       uint32_t& r2, uint32_t& r3, uint32_t a) {
    asm volatile("ldmatrix.sync.aligned.m8n8.x4.shared.b16 {%0,%1,%2,%3}, [%4];"
                 : "=r"(r0), "=r"(r1), "=r"(r2), "=r"(r3) : "r"(a));
}

__device__ __forceinline__ void mma16816(float& c0, float& c1, float& c2, float& c3,
                                         uint32_t a0, uint32_t a1, uint32_t a2, uint32_t a3,
                                         uint32_t b0, uint32_t b1) {
    asm volatile(
        "mma.sync.aligned.m16n8k16.row.col.f32.f16.f16.f32 "
        "{%0,%1,%2,%3}, {%4,%5,%6,%7}, {%8,%9}, {%0,%1,%2,%3};"
        : "+f"(c0), "+f"(c1), "+f"(c2), "+f"(c3)
        : "r"(a0), "r"(a1), "r"(a2), "r"(a3), "r"(b0), "r"(b1));
}

// ---------------- HMMA GEMM (fp16 2-product) ---------------------------------
// C[m][n] = alpha * sum_k A[m][k] * B[n][k]   (fp32 accumulate)
// 2-product fp16 split: (Ah + Al) * Bh.  Dropped A*Bl ~ 2^-12 relative.
// Per stage holds 3 plane tiles (Ah, Al, Bh). BM=BN=128, BK=32, 3-stage pipe.
// EPI=0: fp32 -> Cf.  EPI=1: fp16 hi/lo planes -> Ch/Cl.
// EPI=3: merged QKV — blockIdx.z selects B (z0:Bh, z1:Bh2, z2:Bh3) and output
//        (z0: Ch/Cl, z1: Ch2/Cl2, z2: fp32 Cf).
// CSKIP: skip tiles strictly above diagonal. CK: truncate K at (by+1)*128.
// Causal grids permute by with (5*by)%16 for last-wave balance.
#define ROWB   80u                 // padded SMEM row stride (32 fp16 + 8 pad)
#define TILEB  (128u * ROWB)       // 10240 B per plane tile
#define STAGEB (3u * TILEB)        // 30720 B per stage (Ah, Al, Bh)
#define DYN_SMEM (3 * 30720)       // 92160 B

template<bool CSKIP, bool CK, int EPI>
__global__ void __launch_bounds__(256) gemm_mma(
    const fp16* __restrict__ Ah, const fp16* __restrict__ Al,
    const fp16* __restrict__ Bh,
    float* __restrict__ Cf, fp16* __restrict__ Ch, fp16* __restrict__ Cl,
    const fp16* __restrict__ Bh2, const fp16* __restrict__ Bh3,
    fp16* __restrict__ Ch2, fp16* __restrict__ Cl2,
    int Krow, int ldc, long sA, long sB, long sC, float alpha)
{
    // launch-order balance permutation for causal grids (grid.y == 16)
    const int by = (CSKIP || CK) ? (int)((blockIdx.y * 5u) & 15u)
                                 : (int)blockIdx.y;
    if (CSKIP && (int)blockIdx.x > by) return;

    extern __shared__ char dsm[];
    const uint32_t sbase = smem_u32(dsm);

    const int tid  = threadIdx.x;
    const int wid  = tid >> 5, lane = tid & 31;
    const int wm   = wid >> 2, wn = wid & 3;        // 2 x 4 warp grid
    const int m0   = by * 128;
    const int n0   = blockIdx.x * 128;
    const int zid  = blockIdx.z;

    const fp16* AhP = Ah + (long)zid * sA;
    const fp16* AlP = Al + (long)zid * sA;
    const fp16* BhP = Bh;
    if (EPI == 3) {
        if (zid == 1)      BhP = Bh2;
        else if (zid == 2) BhP = Bh3;
    } else {
        BhP += (long)zid * sB;
    }

    const int kEnd = CK ? min(Krow, (by + 1) * 128) : Krow;
    const int T    = kEnd >> 5;      // one iteration per 32-wide k-slab

    // loader coords: thread handles rows (tid>>2) and (tid>>2)+64, chunk tid&3
    const int lrow = tid >> 2;
    const int lch  = tid & 3;

    float c[4][4][4];
    #pragma unroll
    for (int i = 0; i < 4; i++)
        #pragma unroll
        for (int j = 0; j < 4; j++)
            #pragma unroll
            for (int e = 0; e < 4; e++) c[i][j][e] = 0.f;

    // ---- slab load: Ah, Al, Bh tiles for k-slab t into stage s ----
    auto load_slab = [&](int t, int s) {
        const int k0 = t << 5;
        const uint32_t st = sbase + (uint32_t)s * STAGEB;
        #pragma unroll
        for (int h = 0; h < 2; h++) {
            const int row = lrow + h * 64;
            const uint32_t doff = (uint32_t)row * ROWB + (uint32_t)lch * 16u;
            const size_t aoff = (size_t)(m0 + row) * Krow + k0 + lch * 8;
            const size_t boff = (size_t)(n0 + row) * Krow + k0 + lch * 8;
            cp16(st + doff,             AhP + aoff);
            cp16(st + TILEB + doff,     AlP + aoff);
            cp16(st + 2 * TILEB + doff, BhP + boff);
        }
    };

    // prologue: stages 0,1
    load_slab(0, 0); CP_COMMIT();
    if (T > 1) { load_slab(1, 1); } CP_COMMIT();

    // ldmatrix lane addressing
    const uint32_t frow = ((lane >> 3) & 1) * 8 + (lane & 7);  // row-in-16
    const uint32_t fk   = ((lane >> 4) & 1) * 8;               // k-offset 0/8

    for (int t = 0; t < T; t++) {
        CP_WAIT(1);
        __syncthreads();
        // stage (t+2)%3 was last READ in iteration t-1; every warp passed this
        // sync only after finishing t-1's compute, so overwriting it is safe.
        if (t + 2 < T) load_slab(t + 2, (t + 2) % 3);
        CP_COMMIT();

        const uint32_t st = sbase + (uint32_t)(t % 3) * STAGEB;
        const uint32_t ahs = st;
        const uint32_t als = st + TILEB;
        const uint32_t bhs = st + 2 * TILEB;

        #pragma unroll
        for (int ks = 0; ks < 32; ks += 16) {
            uint32_t ah[4][4], al[4][4], bh[2][4];
            const uint32_t kcb = (uint32_t)(ks + fk) * 2u;
            #pragma unroll
            for (int i = 0; i < 4; i++) {
                const uint32_t ro = (uint32_t)(wm * 64 + i * 16 + frow) * ROWB + kcb;
                ldm_x4(ah[i][0], ah[i][1], ah[i][2], ah[i][3], ahs + ro);
                ldm_x4(al[i][0], al[i][1], al[i][2], al[i][3], als + ro);
            }
            #pragma unroll
            for (int j = 0; j < 2; j++) {
                const uint32_t ro = (uint32_t)(wn * 32 + j * 16 + frow) * ROWB + kcb;
                ldm_x4(bh[j][0], bh[j][1], bh[j][2], bh[j][3], bhs + ro);
            }
            #pragma unroll
            for (int i = 0; i < 4; i++)
                #pragma unroll
                for (int jn = 0; jn < 4; jn++) {
                    const int jh = jn >> 1, sub = jn & 1;
                    float* cc = c[i][jn];
                    mma16816(cc[0], cc[1], cc[2], cc[3],
                             ah[i][0], ah[i][1], ah[i][2], ah[i][3],
                             bh[jh][sub], bh[jh][sub + 2]);
                    mma16816(cc[0], cc[1], cc[2], cc[3],
                             al[i][0], al[i][1], al[i][2], al[i][3],
                             bh[jh][sub], bh[jh][sub + 2]);
                }
        }
        // no bottom sync: top-of-loop sync of iteration t+1 provides the
        // ordering before any warp's cp.async can touch this stage again.
    }

    // ---- epilogue: accumulator quad layout -> direct global stores ----
    const int g   = lane >> 2;        // row within 8
    const int tg  = lane & 3;         // col pair
    const long zC = (EPI == 3) ? 0 : (long)zid * sC;

    float* CfP = Cf;
    fp16*  ChP = Ch;
    fp16*  ClP = Cl;
    if (EPI == 3 && zid == 1) { ChP = Ch2; ClP = Cl2; }
    const bool fp32out = (EPI == 0) || (EPI == 3 && zid == 2);

    #pragma unroll
    for (int i = 0; i < 4; i++) {
        #pragma unroll
        for (int jn = 0; jn < 4; jn++) {
            const int row = m0 + wm * 64 + i * 16 + g;
            const int col = n0 + wn * 32 + jn * 8 + tg * 2;
            #pragma unroll
            for (int half = 0; half < 2; half++) {
                const size_t o = (size_t)(row + half * 8) * ldc + zC + col;
                const float v0 = alpha * c[i][jn][half * 2 + 0];
                const float v1 = alpha * c[i][jn][half * 2 + 1];
                if (fp32out) {
                    float2 f2; f2.x = v0; f2.y = v1;
                    *(float2*)(CfP + o) = f2;
                } else {
                    const fp16 h0 = __float2half(v0);
                    const fp16 h1 = __float2half(v1);
                    __half2 hh; hh.x = h0; hh.y = h1;
                    *(__half2*)(ChP + o) = hh;
                    __half2 ll;
                    ll.x = __float2half(v0 - __half2float(h0));
                    ll.y = __float2half(v1 - __half2float(h1));
                    *(__half2*)(ClP + o) = ll;
                }
            }
        }
    }
}

// ---------------- merged split: x (hi/lo) + Wq/Wk/Wv (hi only) --------------
#define NX (MTOT * D)      // 8388608
#define NW (D * D)         // 1048576 = 2^20
__global__ void __launch_bounds__(256) conv_split_all(
    const float* __restrict__ x,  const float* __restrict__ wq,
    const float* __restrict__ wk, const float* __restrict__ wv,
    fp16* __restrict__ xh,  fp16* __restrict__ xl,
    fp16* __restrict__ qh_, fp16* __restrict__ kh_, fp16* __restrict__ vh_)
{
    long i = (long)blockIdx.x * 256 + threadIdx.x;
    if (i < NX) {
        float v = x[i];
        fp16 hi = __float2half(v);
        xh[i] = hi;
        xl[i] = __float2half(v - __half2float(hi));
    } else {
        long r = i - NX;
        int seg = (int)(r >> 20);       // NW = 2^20
        long j = r & (NW - 1);
        const float* s;
        fp16* h;
        if (seg == 0)      { s = wq; h = qh_; }
        else if (seg == 1) { s = wk; h = kh_; }
        else               { s = wv; h = vh_; }
        h[j] = __float2half(s[j]);
    }
}

// ---------------- transpose (hi plane only): [z][R][C] -> [z][C][R] ---------
__global__ void __launch_bounds__(256) transpose_hi(
    const float* __restrict__ src, fp16* __restrict__ dh,
    int R, int C, long sSrc, long sDst)
{
    __shared__ float t[32][33];
    const int tx = threadIdx.x, ty = threadIdx.y;   // 32 x 8
    const int x0 = blockIdx.x * 32;                 // over C
    const int y0 = blockIdx.y * 32;                 // over R
    const long zb = (long)blockIdx.z;

    #pragma unroll
    for (int j = 0; j < 4; j++)
        t[ty + j * 8][tx] = src[zb * sSrc + (size_t)(y0 + ty + j * 8) * C + x0 + tx];
    __syncthreads();

    #pragma unroll
    for (int j = 0; j < 4; j++) {
        const float v = t[tx][ty + j * 8];
        const size_t o = zb * sDst + (size_t)(x0 + ty + j * 8) * R + y0 + tx;
        dh[o] = __float2half(v);
    }
}

// ---------------- causal softmax (fp32 in, fp16 hi/lo planes out) -----------
__global__ void __launch_bounds__(256) softmax_causal(const float* __restrict__ P,
                                                      fp16* __restrict__ Ph,
                                                      fp16* __restrict__ Pl) {
    const int row = blockIdx.x;            // b * SEQ + i
    const int i = row & (SEQ - 1);
    const float* p = P + (size_t)row * SEQ;
    fp16* ph = Ph + (size_t)row * SEQ;
    fp16* pl = Pl + (size_t)row * SEQ;
    const int n = i + 1;
    const int tid = threadIdx.x;
    __shared__ float red[256];
    __shared__ float rowbuf[SEQ];          // 8KB — hold exp values

    float m = -1e30f;
    for (int j = tid; j < n; j += 256) m = fmaxf(m, p[j]);
    red[tid] = m; __syncthreads();
    for (int s = 128; s > 0; s >>= 1) {
        if (tid < s) red[tid] = fmaxf(red[tid], red[tid + s]);
        __syncthreads();
    }
    m = red[0]; __syncthreads();

    float sum = 0.f;
    for (int j = tid; j < n; j += 256) {
        float e = __expf(p[j] - m);
        rowbuf[j] = e;
        sum += e;
    }
    red[tid] = sum; __syncthreads();
    for (int s = 128; s > 0; s >>= 1) {
        if (tid < s) red[tid] += red[tid + s];
        __syncthreads();
    }
    const float inv = 1.f / red[0];
    __syncthreads();

    for (int j = tid; j < n; j += 256) {
        const float v = rowbuf[j] * inv;
        const fp16 h = __float2half(v);
        ph[j] = h;
        pl[j] = __float2half(v - __half2float(h));
    }
    const fp16 z = __float2half(0.f);
    for (int j = n + tid; j < SEQ; j += 256) { ph[j] = z; pl[j] = z; }
}

// ---------------- launch -----------------------------------------------------
extern "C" void kernel_launch(void* const* d_in, const int* in_sizes, int n_in,
                              void* d_out, int out_size) {
    const float* Wk = (const float*)d_in[0];
    const float* Wq = (const float*)d_in[1];
    const float* Wv = (const float*)d_in[2];
    const float* Wo = (const float*)d_in[3];
    const float* x  = (const float*)d_in[4];
    float* out = (float*)d_out;

    fp16 *xh,*xl,*wqh,*wkh,*wvh,*woth;
    fp16 *qh,*ql,*kh,*kl,*vth,*ph,*pl,*oh,*ol;
    float *vf,*pf;
    cudaGetSymbolAddress((void**)&xh, g_xh);   cudaGetSymbolAddress((void**)&xl, g_xl);
    cudaGetSymbolAddress((void**)&wqh, g_wqh);
    cudaGetSymbolAddress((void**)&wkh, g_wkh);
    cudaGetSymbolAddress((void**)&wvh, g_wvh);
    cudaGetSymbolAddress((void**)&woth, g_woth);
    cudaGetSymbolAddress((void**)&qh, g_qh);   cudaGetSymbolAddress((void**)&ql, g_ql);
    cudaGetSymbolAddress((void**)&kh, g_kh);   cudaGetSymbolAddress((void**)&kl, g_kl);
    cudaGetSymbolAddress((void**)&vf, g_vf);
    cudaGetSymbolAddress((void**)&vth, g_vth);
    cudaGetSymbolAddress((void**)&pf, g_pf);
    cudaGetSymbolAddress((void**)&ph, g_ph);   cudaGetSymbolAddress((void**)&pl, g_pl);
    cudaGetSymbolAddress((void**)&oh, g_oh);   cudaGetSymbolAddress((void**)&ol, g_ol);

    cudaFuncSetAttribute(gemm_mma<false,false,3>, cudaFuncAttributeMaxDynamicSharedMemorySize, DYN_SMEM);
    cudaFuncSetAttribute(gemm_mma<false,false,0>, cudaFuncAttributeMaxDynamicSharedMemorySize, DYN_SMEM);
    cudaFuncSetAttribute(gemm_mma<true ,false,0>, cudaFuncAttributeMaxDynamicSharedMemorySize, DYN_SMEM);
    cudaFuncSetAttribute(gemm_mma<false,true ,1>, cudaFuncAttributeMaxDynamicSharedMemorySize, DYN_SMEM);

    const long SD = (long)SEQ * D;
    const long SS = (long)SEQ * SEQ;

    // split x (hi/lo) + weights (hi) in ONE launch
    conv_split_all<<<(NX + 3 * NW + 255) / 256, 256>>>(
        x, Wq, Wk, Wv, xh, xl, wqh, wkh, wvh);
    // Wo^T hi plane
    transpose_hi<<<dim3(32, 32, 1), dim3(32, 8)>>>(Wo, woth, D, D, 0, 0);

    // merged QKV projection: z selects weight plane + output target
    //   z=0 -> Q planes (qh/ql), z=1 -> K planes (kh/kl), z=2 -> V fp32 (vf)
    gemm_mma<false,false,3><<<dim3(8, 64, 3), 256, DYN_SMEM>>>(
        xh, xl, wqh, vf, qh, ql,
        wkh, wvh, kh, kl,
        D, D, 0, 0, 0, 1.f);

    // V^T hi plane per batch: [SEQ,D] -> [D,SEQ]
    transpose_hi<<<dim3(D / 32, SEQ / 32, BATCH), dim3(32, 8)>>>(
        vf, vth, SEQ, D, SD, SD);

    // scores P = Q K^T / 32 (batched, causal tile-skip, by-permuted)
    gemm_mma<true,false,0><<<dim3(16, 16, BATCH), 256, DYN_SMEM>>>(
        qh, ql, kh, pf, nullptr, nullptr,
        nullptr, nullptr, nullptr, nullptr,
        D, SEQ, SD, SD, SS, 0.03125f);

    // causal softmax -> P planes (zero-filled upper triangle)
    softmax_causal<<<BATCH * SEQ, 256>>>(pf, ph, pl);

    // O = P V (batched, causal K-truncation, by-permuted); B = V^T hi plane
    gemm_mma<false,true,1><<<dim3(8, 16, BATCH), 256, DYN_SMEM>>>(
        ph, pl, vth, nullptr, oh, ol,
        nullptr, nullptr, nullptr, nullptr,
        SEQ, D, SS, SD, SD, 1.f);

    // out = O Wo ; B = Wo^T hi plane [n][k]
    gemm_mma<false,false,0><<<dim3(8, 64, 1), 256, DYN_SMEM>>>(
        oh, ol, woth, out, nullptr, nullptr,
        nullptr, nullptr, nullptr, nullptr,
        D, D, 0, 0, 0, 1.f);
}